// round 1
// baseline (speedup 1.0000x reference)
#include <cuda_runtime.h>
#include <math.h>

#define BTOT 262144
#define SDIM 100
#define HID  256
#define ENCD 128
#define NB1  4096   // BTOT/64

// Scratch (device globals — no allocation allowed)
__device__ float g_h  [(size_t)BTOT * HID];    // post-ReLU hidden [B,256]
__device__ float g_enc[(size_t)BTOT * ENCD];   // encoder output  [B,128]
__device__ float g_eh [(size_t)BTOT * 640];    // expert hidden   [B,10*64]
__device__ float g_psum[HID * NB1];            // [c][block] partial sums
__device__ float g_psq [HID * NB1];            // [c][block] partial sumsq
__device__ float g_A [HID];                    // rstd*gamma
__device__ float g_Bb[HID];                    // beta - mu*rstd*gamma

// ---------------------------------------------------------------------------
// K1: h = relu(state @ W1 + b1)  [B,100]@[100,256], + per-block channel stats
// Block: 64 rows x 256 cols, 256 threads, 8x8 microtile, K chunks of 25.
// ---------------------------------------------------------------------------
__global__ __launch_bounds__(256, 1)
void k_gemm1(const float* __restrict__ state,
             const float* __restrict__ W1,
             const float* __restrict__ b1) {
    __shared__ float pool[8000];     // [0,6400): W1 chunk [25][256]; [6400,8000): state chunk [64][25]
    float* s_w = pool;
    float* s_state = pool + 6400;
    const int t = threadIdx.x;
    const int blk = blockIdx.x;
    const int row0 = blk * 64;
    const int tr = t >> 5, tc = t & 31;

    float acc[8][8];
#pragma unroll
    for (int r = 0; r < 8; r++)
#pragma unroll
        for (int c = 0; c < 8; c++) acc[r][c] = 0.f;

    for (int ch = 0; ch < 4; ch++) {
        const int kk0 = ch * 25;
        __syncthreads();
        // W1 chunk: rows kk0..kk0+24 are contiguous (25*256 floats = 1600 float4)
        const float4* wsrc = (const float4*)(W1 + kk0 * HID);
        for (int i = t; i < 1600; i += 256)
            ((float4*)s_w)[i] = wsrc[i];
        // state chunk: 64 rows x 25 cols
        for (int i = t; i < 1600; i += 256) {
            int r = i / 25, c = i - r * 25;
            s_state[i] = state[(size_t)(row0 + r) * SDIM + kk0 + c];
        }
        __syncthreads();
#pragma unroll 5
        for (int kk = 0; kk < 25; kk++) {
            float a[8], b[8];
#pragma unroll
            for (int r = 0; r < 8; r++) a[r] = s_state[(tr * 8 + r) * 25 + kk];
#pragma unroll
            for (int c = 0; c < 8; c++) b[c] = s_w[kk * 256 + tc + 32 * c];
#pragma unroll
            for (int r = 0; r < 8; r++)
#pragma unroll
                for (int c = 0; c < 8; c++)
                    acc[r][c] = fmaf(a[r], b[c], acc[r][c]);
        }
    }
    __syncthreads();   // done with compute reads of pool; reuse it for reduction

    float cs[8], cq[8];
#pragma unroll
    for (int c = 0; c < 8; c++) { cs[c] = 0.f; cq[c] = 0.f; }
#pragma unroll
    for (int c = 0; c < 8; c++) {
        const int col = tc + 32 * c;
        const float bias = b1[col];
#pragma unroll
        for (int r = 0; r < 8; r++) {
            float v = fmaxf(acc[r][c] + bias, 0.f);
            g_h[(size_t)(row0 + tr * 8 + r) * HID + col] = v;
            cs[c] += v;
            cq[c] += v * v;
        }
    }
    // deterministic block reduction over the 8 tr-groups
#pragma unroll
    for (int c = 0; c < 8; c++) {
        pool[tr * 256 + tc + 32 * c]        = cs[c];
        pool[2048 + tr * 256 + tc + 32 * c] = cq[c];
    }
    __syncthreads();
    {
        float S = 0.f, Q = 0.f;
#pragma unroll
        for (int r = 0; r < 8; r++) {
            S += pool[r * 256 + t];
            Q += pool[2048 + r * 256 + t];
        }
        g_psum[t * NB1 + blk] = S;
        g_psq [t * NB1 + blk] = Q;
    }
}

// ---------------------------------------------------------------------------
// K2: finalize BN stats -> folded affine A, Bb. One block per channel.
// ---------------------------------------------------------------------------
__global__ __launch_bounds__(256, 1)
void k_stats(const float* __restrict__ gamma, const float* __restrict__ beta) {
    const int c = blockIdx.x, t = threadIdx.x;
    float s = 0.f, q = 0.f;
    for (int i = t; i < NB1; i += 256) {
        s += g_psum[c * NB1 + i];
        q += g_psq [c * NB1 + i];
    }
#pragma unroll
    for (int off = 16; off; off >>= 1) {
        s += __shfl_xor_sync(0xffffffffu, s, off);
        q += __shfl_xor_sync(0xffffffffu, q, off);
    }
    __shared__ float ss[8], sq[8];
    if ((t & 31) == 0) { ss[t >> 5] = s; sq[t >> 5] = q; }
    __syncthreads();
    if (t == 0) {
        float S = 0.f, Q = 0.f;
#pragma unroll
        for (int wv = 0; wv < 8; wv++) { S += ss[wv]; Q += sq[wv]; }
        const float inv_n = 1.f / (float)BTOT;
        float mu = S * inv_n;
        float var = Q * inv_n - mu * mu;
        float rstd = rsqrtf(var + 1e-5f);
        float gg = gamma[c];
        g_A [c] = rstd * gg;
        g_Bb[c] = beta[c] - mu * rstd * gg;
    }
}

// ---------------------------------------------------------------------------
// K3: enc = tanh(BN(h) @ W2 + b2)  [B,256]@[256,128]
// Block: 64 rows x 128 cols, 8x4 microtile, K chunks of 32, normalize-on-load.
// ---------------------------------------------------------------------------
__global__ __launch_bounds__(256, 1)
void k_gemm2(const float* __restrict__ W2, const float* __restrict__ b2) {
    __shared__ float s_h[64 * 32];
    __shared__ float s_w[32 * 128];
    const int t = threadIdx.x;
    const int row0 = blockIdx.x * 64;
    const int tr = t >> 5, tc = t & 31;
    float acc[8][4];
#pragma unroll
    for (int r = 0; r < 8; r++)
#pragma unroll
        for (int c = 0; c < 4; c++) acc[r][c] = 0.f;

    for (int ch = 0; ch < 8; ch++) {
        const int kk0 = ch * 32;
        __syncthreads();
        for (int i = t; i < 512; i += 256) {
            int r = i >> 3, f = i & 7;
            int c = kk0 + f * 4;
            float4 v = *(const float4*)(g_h + (size_t)(row0 + r) * HID + c);
            v.x = fmaf(v.x, g_A[c],     g_Bb[c]);
            v.y = fmaf(v.y, g_A[c + 1], g_Bb[c + 1]);
            v.z = fmaf(v.z, g_A[c + 2], g_Bb[c + 2]);
            v.w = fmaf(v.w, g_A[c + 3], g_Bb[c + 3]);
            ((float4*)s_h)[i] = v;
        }
        const float4* wsrc = (const float4*)(W2 + kk0 * ENCD);
        for (int i = t; i < 1024; i += 256)
            ((float4*)s_w)[i] = wsrc[i];
        __syncthreads();
#pragma unroll 8
        for (int kk = 0; kk < 32; kk++) {
            float a[8], b[4];
#pragma unroll
            for (int r = 0; r < 8; r++) a[r] = s_h[(tr * 8 + r) * 32 + kk];
#pragma unroll
            for (int c = 0; c < 4; c++) b[c] = s_w[kk * 128 + tc + 32 * c];
#pragma unroll
            for (int r = 0; r < 8; r++)
#pragma unroll
                for (int c = 0; c < 4; c++)
                    acc[r][c] = fmaf(a[r], b[c], acc[r][c]);
        }
    }
#pragma unroll
    for (int c = 0; c < 4; c++) {
        const int col = tc + 32 * c;
        const float bias = b2[col];
#pragma unroll
        for (int r = 0; r < 8; r++)
            g_enc[(size_t)(row0 + tr * 8 + r) * ENCD + col] = tanhf(acc[r][c] + bias);
    }
}

// ---------------------------------------------------------------------------
// K4a: eh[:, k*64+j] = relu(enc @ We1[k] + be1[k])  for all 10 experts.
// Block: 64 rows; loop over 5 expert-pairs (128 j-cols each), e-chunks of 32.
// ---------------------------------------------------------------------------
__global__ __launch_bounds__(256, 1)
void k_expert(const float* __restrict__ We1, const float* __restrict__ be1) {
    __shared__ float s_e[64 * 32];
    __shared__ float s_w[32 * 128];
    const int t = threadIdx.x;
    const int row0 = blockIdx.x * 64;
    const int tr = t >> 5, tc = t & 31;

    for (int g = 0; g < 5; g++) {
        float acc[8][4];
#pragma unroll
        for (int r = 0; r < 8; r++)
#pragma unroll
            for (int c = 0; c < 4; c++) acc[r][c] = 0.f;

        for (int ch = 0; ch < 4; ch++) {
            const int e0 = ch * 32;
            __syncthreads();
            for (int i = t; i < 512; i += 256) {
                int r = i >> 3, f = i & 7;
                ((float4*)s_e)[i] =
                    *(const float4*)(g_enc + (size_t)(row0 + r) * ENCD + e0 + f * 4);
            }
#pragma unroll
            for (int h = 0; h < 2; h++) {
                const float4* wsrc =
                    (const float4*)(We1 + (size_t)((2 * g + h) * 128 + e0) * 64);
                for (int i = t; i < 512; i += 256) {
                    int e = i >> 4, j4 = i & 15;
                    ((float4*)s_w)[e * 32 + h * 16 + j4] = wsrc[i];
                }
            }
            __syncthreads();
#pragma unroll 8
            for (int e = 0; e < 32; e++) {
                float a[8], b[4];
#pragma unroll
                for (int r = 0; r < 8; r++) a[r] = s_e[(tr * 8 + r) * 32 + e];
#pragma unroll
                for (int c = 0; c < 4; c++) b[c] = s_w[e * 128 + tc + 32 * c];
#pragma unroll
                for (int r = 0; r < 8; r++)
#pragma unroll
                    for (int c = 0; c < 4; c++)
                        acc[r][c] = fmaf(a[r], b[c], acc[r][c]);
            }
        }
#pragma unroll
        for (int c = 0; c < 4; c++) {
            const int j2 = tc + 32 * c;                 // k*64+j == g*128 + j2
            const float bias = be1[g * 128 + j2];
#pragma unroll
            for (int r = 0; r < 8; r++) {
                float v = fmaxf(acc[r][c] + bias, 0.f);
                g_eh[(size_t)(row0 + tr * 8 + r) * 640 + g * 128 + j2] = v;
            }
        }
    }
}

// ---------------------------------------------------------------------------
// K4b: distances -> softmax strengths -> fold into eh -> habit GEMM -> output.
// Warp per row (8 rows / block).
// ---------------------------------------------------------------------------
__global__ __launch_bounds__(256, 1)
void k_tail(const float* __restrict__ We2, const float* __restrict__ be2,
            const float* __restrict__ att, float* __restrict__ out) {
    const int t = threadIdx.x;
    const int w = t >> 5, lane = t & 31;
    const size_t row = (size_t)blockIdx.x * 8 + w;

    float4 e4 = *(const float4*)(g_enc + row * ENCD + lane * 4);

    float dist[10];
#pragma unroll
    for (int k = 0; k < 10; k++) {
        float4 a4 = *(const float4*)(att + k * ENCD + lane * 4);
        float dx = e4.x - a4.x, dy = e4.y - a4.y;
        float dz = e4.z - a4.z, dw = e4.w - a4.w;
        float p = dx * dx + dy * dy + dz * dz + dw * dw;
#pragma unroll
        for (int off = 16; off; off >>= 1) p += __shfl_xor_sync(0xffffffffu, p, off);
        dist[k] = sqrtf(p);
    }
    float dmin = dist[0];
#pragma unroll
    for (int k = 1; k < 10; k++) dmin = fminf(dmin, dist[k]);
    float s[10]; float Z = 0.f;
#pragma unroll
    for (int k = 0; k < 10; k++) {
        s[k] = expf(-2.f * (dist[k] - dmin));   // -dist/TEMP, TEMP=0.5
        Z += s[k];
    }
    const float invZ = 1.f / Z;

    float p[10];
#pragma unroll
    for (int a = 0; a < 10; a++) p[a] = 0.f;
#pragma unroll
    for (int chk = 0; chk < 5; chk++) {
        const int j0 = chk * 128 + lane * 4;    // global j index; k = j/64
        float4 eh4 = *(const float4*)(g_eh + row * 640 + j0);
        const float sk = (lane < 16) ? s[2 * chk] : s[2 * chk + 1];
        const float ev[4] = {eh4.x * sk, eh4.y * sk, eh4.z * sk, eh4.w * sk};
#pragma unroll
        for (int i = 0; i < 4; i++) {
            const float2* w2p = (const float2*)(We2 + (size_t)(j0 + i) * 10);
#pragma unroll
            for (int a2 = 0; a2 < 5; a2++) {
                float2 wv = w2p[a2];
                p[2 * a2]     = fmaf(ev[i], wv.x, p[2 * a2]);
                p[2 * a2 + 1] = fmaf(ev[i], wv.y, p[2 * a2 + 1]);
            }
        }
    }
#pragma unroll
    for (int off = 16; off; off >>= 1)
#pragma unroll
        for (int a = 0; a < 10; a++) p[a] += __shfl_xor_sync(0xffffffffu, p[a], off);
    // + sum_k s_k * be2[k]
#pragma unroll
    for (int k = 0; k < 10; k++) {
        const float2* bp = (const float2*)(be2 + k * 10);
        const float sk = s[k];
#pragma unroll
        for (int a2 = 0; a2 < 5; a2++) {
            float2 bv = bp[a2];
            p[2 * a2]     = fmaf(sk, bv.x, p[2 * a2]);
            p[2 * a2 + 1] = fmaf(sk, bv.y, p[2 * a2 + 1]);
        }
    }
#pragma unroll
    for (int a = 0; a < 10; a++)
        if (lane == a) out[row * 10 + a] = p[a] * invZ;
}

// ---------------------------------------------------------------------------
extern "C" void kernel_launch(void* const* d_in, const int* in_sizes, int n_in,
                              void* d_out, int out_size) {
    const float* state = (const float*)d_in[0];
    const float* W1    = (const float*)d_in[1];
    const float* b1    = (const float*)d_in[2];
    const float* gamma = (const float*)d_in[3];
    const float* beta  = (const float*)d_in[4];
    const float* W2    = (const float*)d_in[5];
    const float* b2    = (const float*)d_in[6];
    const float* We1   = (const float*)d_in[7];
    const float* be1   = (const float*)d_in[8];
    const float* We2   = (const float*)d_in[9];
    const float* be2   = (const float*)d_in[10];
    const float* att   = (const float*)d_in[11];
    float* out = (float*)d_out;

    k_gemm1 <<<NB1,   256>>>(state, W1, b1);
    k_stats <<<HID,   256>>>(gamma, beta);
    k_gemm2 <<<NB1,   256>>>(W2, b2);
    k_expert<<<NB1,   256>>>(We1, be1);
    k_tail  <<<BTOT/8,256>>>(We2, be2, att, out);
}

// round 2
// speedup vs baseline: 1.0004x; 1.0004x over previous
#include <cuda_runtime.h>
#include <math.h>

#define BTOT 262144
#define SDIM 100
#define HID  256
#define ENCD 128
#define NB1  4096   // BTOT/64

// Scratch (device globals — no allocation allowed)
__device__ float g_h  [(size_t)BTOT * HID];    // post-ReLU hidden [B,256]
__device__ float g_enc[(size_t)BTOT * ENCD];   // encoder output  [B,128]
__device__ float g_eh [(size_t)BTOT * 640];    // expert hidden   [B,10*64]
__device__ float g_psum[HID * NB1];            // [c][block] partial sums
__device__ float g_psq [HID * NB1];            // [c][block] partial sumsq
__device__ float g_A [HID];                    // rstd*gamma
__device__ float g_Bb[HID];                    // beta - mu*rstd*gamma

// ---------------------------------------------------------------------------
// K1: h = relu(state @ W1 + b1)  [B,100]@[100,256], + per-block channel stats
// Block: 64 rows x 256 cols, 256 threads, 8x8 microtile, K chunks of 25.
// ---------------------------------------------------------------------------
__global__ __launch_bounds__(256, 1)
void k_gemm1(const float* __restrict__ state,
             const float* __restrict__ W1,
             const float* __restrict__ b1) {
    __shared__ float pool[8000];     // [0,6400): W1 chunk [25][256]; [6400,8000): state chunk [64][25]
    float* s_w = pool;
    float* s_state = pool + 6400;
    const int t = threadIdx.x;
    const int blk = blockIdx.x;
    const int row0 = blk * 64;
    const int tr = t >> 5, tc = t & 31;

    float acc[8][8];
#pragma unroll
    for (int r = 0; r < 8; r++)
#pragma unroll
        for (int c = 0; c < 8; c++) acc[r][c] = 0.f;

    for (int ch = 0; ch < 4; ch++) {
        const int kk0 = ch * 25;
        __syncthreads();
        // W1 chunk: rows kk0..kk0+24 are contiguous (25*256 floats = 1600 float4)
        const float4* wsrc = (const float4*)(W1 + kk0 * HID);
        for (int i = t; i < 1600; i += 256)
            ((float4*)s_w)[i] = wsrc[i];
        // state chunk: 64 rows x 25 cols
        for (int i = t; i < 1600; i += 256) {
            int r = i / 25, c = i - r * 25;
            s_state[i] = state[(size_t)(row0 + r) * SDIM + kk0 + c];
        }
        __syncthreads();
#pragma unroll 5
        for (int kk = 0; kk < 25; kk++) {
            float a[8], b[8];
#pragma unroll
            for (int r = 0; r < 8; r++) a[r] = s_state[(tr * 8 + r) * 25 + kk];
#pragma unroll
            for (int c = 0; c < 8; c++) b[c] = s_w[kk * 256 + tc + 32 * c];
#pragma unroll
            for (int r = 0; r < 8; r++)
#pragma unroll
                for (int c = 0; c < 8; c++)
                    acc[r][c] = fmaf(a[r], b[c], acc[r][c]);
        }
    }
    __syncthreads();   // done with compute reads of pool; reuse it for reduction

    float cs[8], cq[8];
#pragma unroll
    for (int c = 0; c < 8; c++) { cs[c] = 0.f; cq[c] = 0.f; }
#pragma unroll
    for (int c = 0; c < 8; c++) {
        const int col = tc + 32 * c;
        const float bias = b1[col];
#pragma unroll
        for (int r = 0; r < 8; r++) {
            float v = fmaxf(acc[r][c] + bias, 0.f);
            g_h[(size_t)(row0 + tr * 8 + r) * HID + col] = v;
            cs[c] += v;
            cq[c] += v * v;
        }
    }
    // deterministic block reduction over the 8 tr-groups
#pragma unroll
    for (int c = 0; c < 8; c++) {
        pool[tr * 256 + tc + 32 * c]        = cs[c];
        pool[2048 + tr * 256 + tc + 32 * c] = cq[c];
    }
    __syncthreads();
    {
        float S = 0.f, Q = 0.f;
#pragma unroll
        for (int r = 0; r < 8; r++) {
            S += pool[r * 256 + t];
            Q += pool[2048 + r * 256 + t];
        }
        g_psum[t * NB1 + blk] = S;
        g_psq [t * NB1 + blk] = Q;
    }
}

// ---------------------------------------------------------------------------
// K2: finalize BN stats -> folded affine A, Bb. One block per channel.
// ---------------------------------------------------------------------------
__global__ __launch_bounds__(256, 1)
void k_stats(const float* __restrict__ gamma, const float* __restrict__ beta) {
    const int c = blockIdx.x, t = threadIdx.x;
    float s = 0.f, q = 0.f;
    for (int i = t; i < NB1; i += 256) {
        s += g_psum[c * NB1 + i];
        q += g_psq [c * NB1 + i];
    }
#pragma unroll
    for (int off = 16; off; off >>= 1) {
        s += __shfl_xor_sync(0xffffffffu, s, off);
        q += __shfl_xor_sync(0xffffffffu, q, off);
    }
    __shared__ float ss[8], sq[8];
    if ((t & 31) == 0) { ss[t >> 5] = s; sq[t >> 5] = q; }
    __syncthreads();
    if (t == 0) {
        float S = 0.f, Q = 0.f;
#pragma unroll
        for (int wv = 0; wv < 8; wv++) { S += ss[wv]; Q += sq[wv]; }
        const float inv_n = 1.f / (float)BTOT;
        float mu = S * inv_n;
        float var = Q * inv_n - mu * mu;
        float rstd = rsqrtf(var + 1e-5f);
        float gg = gamma[c];
        g_A [c] = rstd * gg;
        g_Bb[c] = beta[c] - mu * rstd * gg;
    }
}

// ---------------------------------------------------------------------------
// K3: enc = tanh(BN(h) @ W2 + b2)  [B,256]@[256,128]
// Block: 64 rows x 128 cols, 8x4 microtile, K chunks of 32, normalize-on-load.
// ---------------------------------------------------------------------------
__global__ __launch_bounds__(256, 1)
void k_gemm2(const float* __restrict__ W2, const float* __restrict__ b2) {
    __shared__ float s_h[64 * 32];
    __shared__ float s_w[32 * 128];
    const int t = threadIdx.x;
    const int row0 = blockIdx.x * 64;
    const int tr = t >> 5, tc = t & 31;
    float acc[8][4];
#pragma unroll
    for (int r = 0; r < 8; r++)
#pragma unroll
        for (int c = 0; c < 4; c++) acc[r][c] = 0.f;

    for (int ch = 0; ch < 8; ch++) {
        const int kk0 = ch * 32;
        __syncthreads();
        for (int i = t; i < 512; i += 256) {
            int r = i >> 3, f = i & 7;
            int c = kk0 + f * 4;
            float4 v = *(const float4*)(g_h + (size_t)(row0 + r) * HID + c);
            v.x = fmaf(v.x, g_A[c],     g_Bb[c]);
            v.y = fmaf(v.y, g_A[c + 1], g_Bb[c + 1]);
            v.z = fmaf(v.z, g_A[c + 2], g_Bb[c + 2]);
            v.w = fmaf(v.w, g_A[c + 3], g_Bb[c + 3]);
            ((float4*)s_h)[i] = v;
        }
        const float4* wsrc = (const float4*)(W2 + kk0 * ENCD);
        for (int i = t; i < 1024; i += 256)
            ((float4*)s_w)[i] = wsrc[i];
        __syncthreads();
#pragma unroll 8
        for (int kk = 0; kk < 32; kk++) {
            float a[8], b[4];
#pragma unroll
            for (int r = 0; r < 8; r++) a[r] = s_h[(tr * 8 + r) * 32 + kk];
#pragma unroll
            for (int c = 0; c < 4; c++) b[c] = s_w[kk * 128 + tc + 32 * c];
#pragma unroll
            for (int r = 0; r < 8; r++)
#pragma unroll
                for (int c = 0; c < 4; c++)
                    acc[r][c] = fmaf(a[r], b[c], acc[r][c]);
        }
    }
#pragma unroll
    for (int c = 0; c < 4; c++) {
        const int col = tc + 32 * c;
        const float bias = b2[col];
#pragma unroll
        for (int r = 0; r < 8; r++)
            g_enc[(size_t)(row0 + tr * 8 + r) * ENCD + col] = tanhf(acc[r][c] + bias);
    }
}

// ---------------------------------------------------------------------------
// K4a: eh[:, k*64+j] = relu(enc @ We1[k] + be1[k])  for all 10 experts.
// Block: 64 rows; loop over 5 expert-pairs (128 j-cols each), e-chunks of 32.
// ---------------------------------------------------------------------------
__global__ __launch_bounds__(256, 1)
void k_expert(const float* __restrict__ We1, const float* __restrict__ be1) {
    __shared__ float s_e[64 * 32];
    __shared__ float s_w[32 * 128];
    const int t = threadIdx.x;
    const int row0 = blockIdx.x * 64;
    const int tr = t >> 5, tc = t & 31;

    for (int g = 0; g < 5; g++) {
        float acc[8][4];
#pragma unroll
        for (int r = 0; r < 8; r++)
#pragma unroll
            for (int c = 0; c < 4; c++) acc[r][c] = 0.f;

        for (int ch = 0; ch < 4; ch++) {
            const int e0 = ch * 32;
            __syncthreads();
            for (int i = t; i < 512; i += 256) {
                int r = i >> 3, f = i & 7;
                ((float4*)s_e)[i] =
                    *(const float4*)(g_enc + (size_t)(row0 + r) * ENCD + e0 + f * 4);
            }
#pragma unroll
            for (int h = 0; h < 2; h++) {
                const float4* wsrc =
                    (const float4*)(We1 + (size_t)((2 * g + h) * 128 + e0) * 64);
                for (int i = t; i < 512; i += 256) {
                    int e = i >> 4, j4 = i & 15;
                    ((float4*)s_w)[e * 32 + h * 16 + j4] = wsrc[i];
                }
            }
            __syncthreads();
#pragma unroll 8
            for (int e = 0; e < 32; e++) {
                float a[8], b[4];
#pragma unroll
                for (int r = 0; r < 8; r++) a[r] = s_e[(tr * 8 + r) * 32 + e];
#pragma unroll
                for (int c = 0; c < 4; c++) b[c] = s_w[e * 128 + tc + 32 * c];
#pragma unroll
                for (int r = 0; r < 8; r++)
#pragma unroll
                    for (int c = 0; c < 4; c++)
                        acc[r][c] = fmaf(a[r], b[c], acc[r][c]);
            }
        }
#pragma unroll
        for (int c = 0; c < 4; c++) {
            const int j2 = tc + 32 * c;                 // k*64+j == g*128 + j2
            const float bias = be1[g * 128 + j2];
#pragma unroll
            for (int r = 0; r < 8; r++) {
                float v = fmaxf(acc[r][c] + bias, 0.f);
                g_eh[(size_t)(row0 + tr * 8 + r) * 640 + g * 128 + j2] = v;
            }
        }
    }
}

// ---------------------------------------------------------------------------
// K4b: distances -> softmax strengths -> fold into eh -> habit GEMM -> output.
// Warp per row (8 rows / block).
// ---------------------------------------------------------------------------
__global__ __launch_bounds__(256, 1)
void k_tail(const float* __restrict__ We2, const float* __restrict__ be2,
            const float* __restrict__ att, float* __restrict__ out) {
    const int t = threadIdx.x;
    const int w = t >> 5, lane = t & 31;
    const size_t row = (size_t)blockIdx.x * 8 + w;

    float4 e4 = *(const float4*)(g_enc + row * ENCD + lane * 4);

    float dist[10];
#pragma unroll
    for (int k = 0; k < 10; k++) {
        float4 a4 = *(const float4*)(att + k * ENCD + lane * 4);
        float dx = e4.x - a4.x, dy = e4.y - a4.y;
        float dz = e4.z - a4.z, dw = e4.w - a4.w;
        float p = dx * dx + dy * dy + dz * dz + dw * dw;
#pragma unroll
        for (int off = 16; off; off >>= 1) p += __shfl_xor_sync(0xffffffffu, p, off);
        dist[k] = sqrtf(p);
    }
    float dmin = dist[0];
#pragma unroll
    for (int k = 1; k < 10; k++) dmin = fminf(dmin, dist[k]);
    float s[10]; float Z = 0.f;
#pragma unroll
    for (int k = 0; k < 10; k++) {
        s[k] = expf(-2.f * (dist[k] - dmin));   // -dist/TEMP, TEMP=0.5
        Z += s[k];
    }
    const float invZ = 1.f / Z;

    float p[10];
#pragma unroll
    for (int a = 0; a < 10; a++) p[a] = 0.f;
#pragma unroll
    for (int chk = 0; chk < 5; chk++) {
        const int j0 = chk * 128 + lane * 4;    // global j index; k = j/64
        float4 eh4 = *(const float4*)(g_eh + row * 640 + j0);
        const float sk = (lane < 16) ? s[2 * chk] : s[2 * chk + 1];
        const float ev[4] = {eh4.x * sk, eh4.y * sk, eh4.z * sk, eh4.w * sk};
#pragma unroll
        for (int i = 0; i < 4; i++) {
            const float2* w2p = (const float2*)(We2 + (size_t)(j0 + i) * 10);
#pragma unroll
            for (int a2 = 0; a2 < 5; a2++) {
                float2 wv = w2p[a2];
                p[2 * a2]     = fmaf(ev[i], wv.x, p[2 * a2]);
                p[2 * a2 + 1] = fmaf(ev[i], wv.y, p[2 * a2 + 1]);
            }
        }
    }
#pragma unroll
    for (int off = 16; off; off >>= 1)
#pragma unroll
        for (int a = 0; a < 10; a++) p[a] += __shfl_xor_sync(0xffffffffu, p[a], off);
    // + sum_k s_k * be2[k]
#pragma unroll
    for (int k = 0; k < 10; k++) {
        const float2* bp = (const float2*)(be2 + k * 10);
        const float sk = s[k];
#pragma unroll
        for (int a2 = 0; a2 < 5; a2++) {
            float2 bv = bp[a2];
            p[2 * a2]     = fmaf(sk, bv.x, p[2 * a2]);
            p[2 * a2 + 1] = fmaf(sk, bv.y, p[2 * a2 + 1]);
        }
    }
#pragma unroll
    for (int a = 0; a < 10; a++)
        if (lane == a) out[row * 10 + a] = p[a] * invZ;
}

// ---------------------------------------------------------------------------
extern "C" void kernel_launch(void* const* d_in, const int* in_sizes, int n_in,
                              void* d_out, int out_size) {
    const float* state = (const float*)d_in[0];
    const float* W1    = (const float*)d_in[1];
    const float* b1    = (const float*)d_in[2];
    const float* gamma = (const float*)d_in[3];
    const float* beta  = (const float*)d_in[4];
    const float* W2    = (const float*)d_in[5];
    const float* b2    = (const float*)d_in[6];
    const float* We1   = (const float*)d_in[7];
    const float* be1   = (const float*)d_in[8];
    const float* We2   = (const float*)d_in[9];
    const float* be2   = (const float*)d_in[10];
    const float* att   = (const float*)d_in[11];
    float* out = (float*)d_out;

    k_gemm1 <<<NB1,   256>>>(state, W1, b1);
    k_stats <<<HID,   256>>>(gamma, beta);
    k_gemm2 <<<NB1,   256>>>(W2, b2);
    k_expert<<<NB1,   256>>>(We1, be1);
    k_tail  <<<BTOT/8,256>>>(We2, be2, att, out);
}

// round 3
// speedup vs baseline: 2.5210x; 2.5199x over previous
#include <cuda_runtime.h>
#include <math.h>

#define BTOT 262144
#define NBLK 2048

__device__ float g_h  [(size_t)BTOT * 256];
__device__ float g_enc[(size_t)BTOT * 128];
__device__ float g_s  [(size_t)BTOT * 10];
__device__ float g_psum[256 * NBLK];
__device__ float g_psq [256 * NBLK];
__device__ float g_A [256];
__device__ float g_Bb[256];
__device__ unsigned g_w1hi[128 * 256], g_w1lo[128 * 256];
__device__ unsigned g_w2hi[256 * 128], g_w2lo[256 * 128];
__device__ unsigned g_we1[10 * 128 * 64];
__device__ unsigned g_w2cat[5 * 136 * 16];

__device__ __forceinline__ unsigned f2tf(float f) {
    unsigned u; asm("cvt.rna.tf32.f32 %0, %1;" : "=r"(u) : "f"(f)); return u;
}
__device__ __forceinline__ void mma8(float* c, const unsigned* a, const unsigned* b) {
    asm volatile("mma.sync.aligned.m16n8k8.row.col.f32.tf32.tf32.f32 "
        "{%0,%1,%2,%3},{%4,%5,%6,%7},{%8,%9},{%0,%1,%2,%3};"
        : "+f"(c[0]), "+f"(c[1]), "+f"(c[2]), "+f"(c[3])
        : "r"(a[0]), "r"(a[1]), "r"(a[2]), "r"(a[3]), "r"(b[0]), "r"(b[1]));
}

// ------------------- weight prep (tf32 conversion / splits) -------------------
__global__ void k_prep(const float* __restrict__ W1, const float* __restrict__ W2,
                       const float* __restrict__ We1, const float* __restrict__ We2,
                       const float* __restrict__ be2) {
    int idx = blockIdx.x * blockDim.x + threadIdx.x, st = gridDim.x * blockDim.x;
    for (int i = idx; i < 128 * 256; i += st) {
        int r = i >> 8;
        float v = (r < 100) ? W1[i] : 0.f;
        unsigned h = f2tf(v);
        g_w1hi[i] = h; g_w1lo[i] = f2tf(v - __uint_as_float(h));
    }
    for (int i = idx; i < 256 * 128; i += st) {
        float v = W2[i];
        unsigned h = f2tf(v);
        g_w2hi[i] = h; g_w2lo[i] = f2tf(v - __uint_as_float(h));
    }
    for (int i = idx; i < 10 * 128 * 64; i += st) g_we1[i] = f2tf(We1[i]);
    for (int i = idx; i < 5 * 136 * 16; i += st) {
        int g = i / 2176, r2 = i - g * 2176, j = r2 >> 4, a = r2 & 15;
        float v = 0.f;
        if (a < 10) {
            if (j < 128) v = We2[(size_t)((2 * g + (j >> 6)) * 64 + (j & 63)) * 10 + a];
            else if (j == 128) v = be2[(2 * g) * 10 + a];
            else if (j == 129) v = be2[(2 * g + 1) * 10 + a];
        }
        g_w2cat[i] = f2tf(v);
    }
}

// ------------------- K1: h = relu(state@W1+b1), 3xTF32, + BN partials --------
// grid (2048,2), block tile 128x128, warps 4m x 2n (warp 32x64).
__global__ __launch_bounds__(256)
void k_gemm1(const float* __restrict__ state, const float* __restrict__ b1) {
    extern __shared__ unsigned sm[];
    unsigned* Ahi = sm;             // [128][36]
    unsigned* Alo = sm + 4608;
    unsigned* Bhi = sm + 9216;      // [32][136]
    unsigned* Blo = sm + 13568;     // end 17920 words
    const int t = threadIdx.x, w = t >> 5, lane = t & 31;
    const int gid = lane >> 2, q = lane & 3;
    const int wm = w >> 1, wn = w & 1, rowb = wm * 32, colb = wn * 64;
    const int rb = blockIdx.x, cb = blockIdx.y, row0 = rb * 128;

    float acc[2][8][4];
#pragma unroll
    for (int m = 0; m < 2; m++)
#pragma unroll
        for (int na = 0; na < 8; na++)
#pragma unroll
            for (int j = 0; j < 4; j++) acc[m][na][j] = 0.f;

    for (int ch = 0; ch < 4; ch++) {
        __syncthreads();
        for (int i4 = t; i4 < 1024; i4 += 256) {
            int r = i4 >> 3, f = i4 & 7, sc = ch * 32 + f * 4;
            float4 v = make_float4(0.f, 0.f, 0.f, 0.f);
            if (sc < 100) v = *(const float4*)(state + (size_t)(row0 + r) * 100 + sc);
            unsigned h0 = f2tf(v.x), h1 = f2tf(v.y), h2 = f2tf(v.z), h3 = f2tf(v.w);
            *(uint4*)(Ahi + r * 36 + f * 4) = make_uint4(h0, h1, h2, h3);
            *(uint4*)(Alo + r * 36 + f * 4) = make_uint4(
                f2tf(v.x - __uint_as_float(h0)), f2tf(v.y - __uint_as_float(h1)),
                f2tf(v.z - __uint_as_float(h2)), f2tf(v.w - __uint_as_float(h3)));
        }
        for (int i4 = t; i4 < 1024; i4 += 256) {
            int r = i4 >> 5, c4 = i4 & 31;
            size_t gi = (size_t)(ch * 32 + r) * 256 + cb * 128 + c4 * 4;
            *(uint4*)(Bhi + r * 136 + c4 * 4) = *(const uint4*)(g_w1hi + gi);
            *(uint4*)(Blo + r * 136 + c4 * 4) = *(const uint4*)(g_w1lo + gi);
        }
        __syncthreads();
#pragma unroll
        for (int ks = 0; ks < 4; ks++) {
            unsigned ah[2][4], al[2][4];
#pragma unroll
            for (int m = 0; m < 2; m++) {
                int b = (rowb + 16 * m + gid) * 36 + ks * 8 + q;
                ah[m][0] = Ahi[b]; ah[m][1] = Ahi[b + 288]; ah[m][2] = Ahi[b + 4]; ah[m][3] = Ahi[b + 292];
                al[m][0] = Alo[b]; al[m][1] = Alo[b + 288]; al[m][2] = Alo[b + 4]; al[m][3] = Alo[b + 292];
            }
#pragma unroll
            for (int na = 0; na < 8; na++) {
                int bb = (ks * 8 + q) * 136 + colb + 8 * na + gid;
                unsigned bh[2] = {Bhi[bb], Bhi[bb + 544]};
                unsigned bl[2] = {Blo[bb], Blo[bb + 544]};
#pragma unroll
                for (int m = 0; m < 2; m++) {
                    mma8(acc[m][na], ah[m], bh);
                    mma8(acc[m][na], al[m], bh);
                    mma8(acc[m][na], ah[m], bl);
                }
            }
        }
    }
    __syncthreads();
    float* sums = (float*)sm;     // [4][128]
    float* sqs  = sums + 512;
#pragma unroll
    for (int na = 0; na < 8; na++) {
        int cl = colb + 8 * na + 2 * q, cg = cb * 128 + cl;
        float bias0 = b1[cg], bias1 = b1[cg + 1];
        float p0 = 0.f, p1 = 0.f, q0 = 0.f, q1 = 0.f;
#pragma unroll
        for (int m = 0; m < 2; m++) {
            int r = row0 + rowb + 16 * m + gid;
            float v00 = fmaxf(acc[m][na][0] + bias0, 0.f), v01 = fmaxf(acc[m][na][1] + bias1, 0.f);
            float v10 = fmaxf(acc[m][na][2] + bias0, 0.f), v11 = fmaxf(acc[m][na][3] + bias1, 0.f);
            *(float2*)(g_h + (size_t)r * 256 + cg)       = make_float2(v00, v01);
            *(float2*)(g_h + (size_t)(r + 8) * 256 + cg) = make_float2(v10, v11);
            p0 += v00 + v10; p1 += v01 + v11;
            q0 += v00 * v00 + v10 * v10; q1 += v01 * v01 + v11 * v11;
        }
#pragma unroll
        for (int off = 4; off <= 16; off <<= 1) {
            p0 += __shfl_xor_sync(0xffffffffu, p0, off);
            p1 += __shfl_xor_sync(0xffffffffu, p1, off);
            q0 += __shfl_xor_sync(0xffffffffu, q0, off);
            q1 += __shfl_xor_sync(0xffffffffu, q1, off);
        }
        if (gid == 0) {
            sums[wm * 128 + cl] = p0; sums[wm * 128 + cl + 1] = p1;
            sqs [wm * 128 + cl] = q0; sqs [wm * 128 + cl + 1] = q1;
        }
    }
    __syncthreads();
    if (t < 128) {
        float S = sums[t] + sums[128 + t] + sums[256 + t] + sums[384 + t];
        float Q = sqs[t] + sqs[128 + t] + sqs[256 + t] + sqs[384 + t];
        g_psum[(cb * 128 + t) * NBLK + rb] = S;
        g_psq [(cb * 128 + t) * NBLK + rb] = Q;
    }
}

// ------------------- K2: BN stats finalize -------------------
__global__ __launch_bounds__(256)
void k_stats(const float* __restrict__ gamma, const float* __restrict__ beta) {
    const int c = blockIdx.x, t = threadIdx.x;
    float s = 0.f, qq = 0.f;
    for (int i = t; i < NBLK; i += 256) { s += g_psum[c * NBLK + i]; qq += g_psq[c * NBLK + i]; }
#pragma unroll
    for (int off = 16; off; off >>= 1) {
        s += __shfl_xor_sync(0xffffffffu, s, off);
        qq += __shfl_xor_sync(0xffffffffu, qq, off);
    }
    __shared__ float ss[8], sq[8];
    if ((t & 31) == 0) { ss[t >> 5] = s; sq[t >> 5] = qq; }
    __syncthreads();
    if (t == 0) {
        float S = 0.f, Q = 0.f;
#pragma unroll
        for (int wv = 0; wv < 8; wv++) { S += ss[wv]; Q += sq[wv]; }
        const float inv_n = 1.f / (float)BTOT;
        float mu = S * inv_n;
        float var = Q * inv_n - mu * mu;
        float rstd = rsqrtf(var + 1e-5f);
        float gg = gamma[c];
        g_A[c] = rstd * gg;
        g_Bb[c] = beta[c] - mu * rstd * gg;
    }
}

// ------------------- K3: enc = tanh(BN(h)@W2+b2), 3xTF32 -------------------
__global__ __launch_bounds__(256)
void k_gemm2(const float* __restrict__ b2) {
    extern __shared__ unsigned sm[];
    unsigned* Ahi = sm;
    unsigned* Alo = sm + 4608;
    unsigned* Bhi = sm + 9216;
    unsigned* Blo = sm + 13568;
    float* sAf  = (float*)(sm + 17920);
    float* sBbf = (float*)(sm + 18176);   // end 18432 words
    const int t = threadIdx.x, w = t >> 5, lane = t & 31;
    const int gid = lane >> 2, q = lane & 3;
    const int wm = w >> 1, wn = w & 1, rowb = wm * 32, colb = wn * 64;
    const int row0 = blockIdx.x * 128;

    sAf[t] = g_A[t]; sBbf[t] = g_Bb[t];

    float acc[2][8][4];
#pragma unroll
    for (int m = 0; m < 2; m++)
#pragma unroll
        for (int na = 0; na < 8; na++)
#pragma unroll
            for (int j = 0; j < 4; j++) acc[m][na][j] = 0.f;

    for (int ch = 0; ch < 8; ch++) {
        const int kk0 = ch * 32;
        __syncthreads();
        for (int i4 = t; i4 < 1024; i4 += 256) {
            int r = i4 >> 3, f = i4 & 7, c = kk0 + f * 4;
            float4 v = *(const float4*)(g_h + (size_t)(row0 + r) * 256 + c);
            float x0 = fmaf(v.x, sAf[c], sBbf[c]),   x1 = fmaf(v.y, sAf[c + 1], sBbf[c + 1]);
            float x2 = fmaf(v.z, sAf[c + 2], sBbf[c + 2]), x3 = fmaf(v.w, sAf[c + 3], sBbf[c + 3]);
            unsigned h0 = f2tf(x0), h1 = f2tf(x1), h2 = f2tf(x2), h3 = f2tf(x3);
            *(uint4*)(Ahi + r * 36 + f * 4) = make_uint4(h0, h1, h2, h3);
            *(uint4*)(Alo + r * 36 + f * 4) = make_uint4(
                f2tf(x0 - __uint_as_float(h0)), f2tf(x1 - __uint_as_float(h1)),
                f2tf(x2 - __uint_as_float(h2)), f2tf(x3 - __uint_as_float(h3)));
        }
        for (int i4 = t; i4 < 1024; i4 += 256) {
            int r = i4 >> 5, c4 = i4 & 31;
            size_t gi = (size_t)(kk0 + r) * 128 + c4 * 4;
            *(uint4*)(Bhi + r * 136 + c4 * 4) = *(const uint4*)(g_w2hi + gi);
            *(uint4*)(Blo + r * 136 + c4 * 4) = *(const uint4*)(g_w2lo + gi);
        }
        __syncthreads();
#pragma unroll
        for (int ks = 0; ks < 4; ks++) {
            unsigned ah[2][4], al[2][4];
#pragma unroll
            for (int m = 0; m < 2; m++) {
                int b = (rowb + 16 * m + gid) * 36 + ks * 8 + q;
                ah[m][0] = Ahi[b]; ah[m][1] = Ahi[b + 288]; ah[m][2] = Ahi[b + 4]; ah[m][3] = Ahi[b + 292];
                al[m][0] = Alo[b]; al[m][1] = Alo[b + 288]; al[m][2] = Alo[b + 4]; al[m][3] = Alo[b + 292];
            }
#pragma unroll
            for (int na = 0; na < 8; na++) {
                int bb = (ks * 8 + q) * 136 + colb + 8 * na + gid;
                unsigned bh[2] = {Bhi[bb], Bhi[bb + 544]};
                unsigned bl[2] = {Blo[bb], Blo[bb + 544]};
#pragma unroll
                for (int m = 0; m < 2; m++) {
                    mma8(acc[m][na], ah[m], bh);
                    mma8(acc[m][na], al[m], bh);
                    mma8(acc[m][na], ah[m], bl);
                }
            }
        }
    }
#pragma unroll
    for (int na = 0; na < 8; na++) {
        int cl = colb + 8 * na + 2 * q;
        float bb0 = b2[cl], bb1 = b2[cl + 1];
#pragma unroll
        for (int m = 0; m < 2; m++) {
            int r = row0 + rowb + 16 * m + gid;
            *(float2*)(g_enc + (size_t)r * 128 + cl) =
                make_float2(tanhf(acc[m][na][0] + bb0), tanhf(acc[m][na][1] + bb1));
            *(float2*)(g_enc + (size_t)(r + 8) * 128 + cl) =
                make_float2(tanhf(acc[m][na][2] + bb0), tanhf(acc[m][na][3] + bb1));
        }
    }
}

// ------------------- K4: distances -> softmax strengths -------------------
__global__ __launch_bounds__(256)
void k_soft(const float* __restrict__ att) {
    const int t = threadIdx.x, w = t >> 5, lane = t & 31;
    const size_t row = (size_t)blockIdx.x * 8 + w;
    float4 e4 = *(const float4*)(g_enc + row * 128 + lane * 4);
    float d[10];
#pragma unroll
    for (int k = 0; k < 10; k++) {
        float4 a4 = *(const float4*)(att + k * 128 + lane * 4);
        float dx = e4.x - a4.x, dy = e4.y - a4.y, dz = e4.z - a4.z, dw = e4.w - a4.w;
        float p = dx * dx + dy * dy + dz * dz + dw * dw;
#pragma unroll
        for (int off = 16; off; off >>= 1) p += __shfl_xor_sync(0xffffffffu, p, off);
        d[k] = sqrtf(p);
    }
    float dmin = d[0];
#pragma unroll
    for (int k = 1; k < 10; k++) dmin = fminf(dmin, d[k]);
    float s[10], Z = 0.f;
#pragma unroll
    for (int k = 0; k < 10; k++) { s[k] = expf(-2.f * (d[k] - dmin)); Z += s[k]; }
    float invZ = 1.f / Z;
#pragma unroll
    for (int k = 0; k < 10; k++)
        if (lane == k) g_s[row * 10 + k] = s[k] * invZ;
}

// ------------------- K5: fused experts + gated contraction -> out -----------
// Block 128 rows. Per group g (2 experts, 128 cols): mma1 eh = relu(enc@We1+be1),
// scale by s, append s rows; mma2 out += ehs @ w2cat.
__global__ __launch_bounds__(256)
void k_fused(const float* __restrict__ be1, float* __restrict__ out) {
    extern __shared__ unsigned sm[];
    unsigned* Ae  = sm;                 // enc tf32 [128][132]
    unsigned* buf2 = sm + 16896;        // We1 [128][136] then ehs [128][140]
    unsigned* B2  = sm + 34816;         // w2cat [136][16]
    float* sS  = (float*)(sm + 36992);  // [128][12]
    float* sBe = (float*)(sm + 38528);  // [128]  (total 38656 words)
    const int t = threadIdx.x, w = t >> 5, lane = t & 31;
    const int gid = lane >> 2, q = lane & 3;
    const int wm = w >> 1, wn = w & 1;
    const int row0 = blockIdx.x * 128;

    for (int i4 = t; i4 < 4096; i4 += 256) {
        int r = i4 >> 5, c4 = i4 & 31;
        float4 v = *(const float4*)(g_enc + (size_t)(row0 + r) * 128 + c4 * 4);
        *(uint4*)(Ae + r * 132 + c4 * 4) = make_uint4(f2tf(v.x), f2tf(v.y), f2tf(v.z), f2tf(v.w));
    }
    for (int i = t; i < 1280; i += 256) {
        int r = i / 10, k = i - r * 10;
        sS[r * 12 + k] = g_s[(size_t)(row0 + r) * 10 + k];
    }

    float acc2[2][4];
#pragma unroll
    for (int nf = 0; nf < 2; nf++)
#pragma unroll
        for (int j = 0; j < 4; j++) acc2[nf][j] = 0.f;

    for (int g = 0; g < 5; g++) {
        __syncthreads();
        for (int i4 = t; i4 < 4096; i4 += 256) {
            int e = i4 >> 5, j4 = i4 & 31;
            *(uint4*)(buf2 + e * 136 + j4 * 4) =
                *(const uint4*)(g_we1 + ((size_t)(2 * g + (j4 >> 4)) * 128 + e) * 64 + (j4 & 15) * 4);
        }
        if (t < 128) sBe[t] = be1[g * 128 + t];
        for (int i = t; i < 544; i += 256)
            ((uint4*)B2)[i] = ((const uint4*)(g_w2cat + g * 2176))[i];
        __syncthreads();

        float acc[2][8][4];
#pragma unroll
        for (int m = 0; m < 2; m++)
#pragma unroll
            for (int na = 0; na < 8; na++)
#pragma unroll
                for (int j = 0; j < 4; j++) acc[m][na][j] = 0.f;
#pragma unroll
        for (int ks = 0; ks < 16; ks++) {
            unsigned a[2][4];
#pragma unroll
            for (int m = 0; m < 2; m++) {
                int b = (wm * 32 + 16 * m + gid) * 132 + ks * 8 + q;
                a[m][0] = Ae[b]; a[m][1] = Ae[b + 1056]; a[m][2] = Ae[b + 4]; a[m][3] = Ae[b + 1060];
            }
#pragma unroll
            for (int na = 0; na < 8; na++) {
                int bb = (ks * 8 + q) * 136 + wn * 64 + 8 * na + gid;
                unsigned bh[2] = {buf2[bb], buf2[bb + 544]};
                mma8(acc[0][na], a[0], bh);
                mma8(acc[1][na], a[1], bh);
            }
        }
        __syncthreads();
        // ehs = relu(acc+be1)*s  -> buf2 [128][140] tf32
#pragma unroll
        for (int na = 0; na < 8; na++) {
            int jc = wn * 64 + 8 * na + 2 * q;
            float bia0 = sBe[jc], bia1 = sBe[jc + 1];
            int k0 = 2 * g + (jc >> 6);
#pragma unroll
            for (int m = 0; m < 2; m++) {
                int rr = wm * 32 + 16 * m + gid;
                float s0 = sS[rr * 12 + k0], s1 = sS[(rr + 8) * 12 + k0];
                buf2[rr * 140 + jc]           = f2tf(fmaxf(acc[m][na][0] + bia0, 0.f) * s0);
                buf2[rr * 140 + jc + 1]       = f2tf(fmaxf(acc[m][na][1] + bia1, 0.f) * s0);
                buf2[(rr + 8) * 140 + jc]     = f2tf(fmaxf(acc[m][na][2] + bia0, 0.f) * s1);
                buf2[(rr + 8) * 140 + jc + 1] = f2tf(fmaxf(acc[m][na][3] + bia1, 0.f) * s1);
            }
        }
        for (int i = t; i < 1024; i += 256) {
            int r = i >> 3, jj = 128 + (i & 7);
            float v = (jj == 128) ? sS[r * 12 + 2 * g] : ((jj == 129) ? sS[r * 12 + 2 * g + 1] : 0.f);
            buf2[r * 140 + jj] = f2tf(v);
        }
        __syncthreads();
        // mma2: rows w*16, n=16, K=136
#pragma unroll
        for (int ks = 0; ks < 17; ks++) {
            int b = (w * 16 + gid) * 140 + ks * 8 + q;
            unsigned a2[4] = {buf2[b], buf2[b + 1120], buf2[b + 4], buf2[b + 1124]};
#pragma unroll
            for (int nf = 0; nf < 2; nf++) {
                int bb = (ks * 8 + q) * 16 + nf * 8 + gid;
                unsigned bh[2] = {B2[bb], B2[bb + 64]};
                mma8(acc2[nf], a2, bh);
            }
        }
    }
    size_t r = row0 + w * 16 + gid;
    out[r * 10 + 2 * q]           = acc2[0][0];
    out[r * 10 + 2 * q + 1]       = acc2[0][1];
    out[(r + 8) * 10 + 2 * q]     = acc2[0][2];
    out[(r + 8) * 10 + 2 * q + 1] = acc2[0][3];
    if (q == 0) {
        out[r * 10 + 8] = acc2[1][0];       out[r * 10 + 9] = acc2[1][1];
        out[(r + 8) * 10 + 8] = acc2[1][2]; out[(r + 8) * 10 + 9] = acc2[1][3];
    }
}

// ---------------------------------------------------------------------------
extern "C" void kernel_launch(void* const* d_in, const int* in_sizes, int n_in,
                              void* d_out, int out_size) {
    const float* state = (const float*)d_in[0];
    const float* W1    = (const float*)d_in[1];
    const float* b1    = (const float*)d_in[2];
    const float* gamma = (const float*)d_in[3];
    const float* beta  = (const float*)d_in[4];
    const float* W2    = (const float*)d_in[5];
    const float* b2    = (const float*)d_in[6];
    const float* We1   = (const float*)d_in[7];
    const float* be1   = (const float*)d_in[8];
    const float* We2   = (const float*)d_in[9];
    const float* be2   = (const float*)d_in[10];
    const float* att   = (const float*)d_in[11];
    float* out = (float*)d_out;

    const int SM1 = 17920 * 4, SM2 = 18432 * 4, SMF = 38656 * 4;
    cudaFuncSetAttribute(k_gemm1, cudaFuncAttributeMaxDynamicSharedMemorySize, SM1);
    cudaFuncSetAttribute(k_gemm2, cudaFuncAttributeMaxDynamicSharedMemorySize, SM2);
    cudaFuncSetAttribute(k_fused, cudaFuncAttributeMaxDynamicSharedMemorySize, SMF);

    k_prep <<<256, 256>>>(W1, W2, We1, We2, be2);
    k_gemm1<<<dim3(NBLK, 2), 256, SM1>>>(state, b1);
    k_stats<<<256, 256>>>(gamma, beta);
    k_gemm2<<<NBLK, 256, SM2>>>(b2);
    k_soft <<<BTOT / 8, 256>>>(att);
    k_fused<<<NBLK, 256, SMF>>>(be1, out);
}